// round 13
// baseline (speedup 1.0000x reference)
#include <cuda_runtime.h>
#include <cuda_bf16.h>
#include <math.h>
#include <stdint.h>

#define HD    512
#define GATES 2048
#define NB    1024
#define SEQ   256
#define CH    128
#define NCLS  40
#define NBLK  256          // 16 m-tiles x 16 j-tiles, 2 CTAs/SM
#define NTHR  256
#define NGRP  16           // blocks per barrier group (same mt, all jt)

// smem stage (u32): 64-wide K superchunk. aHi|aLo (64 rows) + bHi|bLo (128 rows)
#define RSTRIDE 36                     // 32 data u32 + 4 pad
#define A_TILE_U32 (64 * RSTRIDE)      // 2304
#define B_TILE_U32 (128 * RSTRIDE)     // 4608
#define STAGE_U32 (2 * A_TILE_U32 + 2 * B_TILE_U32)   // 13824
#define SMEM_SZ (2 * STAGE_U32 * 4)    // 110592 bytes

// precomputed hi/lo bf16 weights, packed per (layer, jt, superchunk) tile [128][64]
#define W0_NCH 10
#define W1_NCH 16
#define W0_TILES (16 * W0_NCH)
#define W1_TILES (16 * W1_NCH)
#define WTILE 8192
#define WN ((W0_TILES + W1_TILES) * WTILE)

// ---------------- persistent device scratch ---------------------------------
__device__ __align__(256) __nv_bfloat16 g_whi[WN];
__device__ __align__(256) __nv_bfloat16 g_wlo[WN];
// x projected layout [t][n][c], split once per launch
__device__ __align__(256) __nv_bfloat16 g_xhi[SEQ * NB * CH];
__device__ __align__(256) __nv_bfloat16 g_xlo[SEQ * NB * CH];
// hidden states as bf16 hi/lo pairs (split once at production)
__device__ __align__(256) __nv_bfloat16 g_h0hi[2][NB * HD];
__device__ __align__(256) __nv_bfloat16 g_h0lo[2][NB * HD];
__device__ __align__(256) __nv_bfloat16 g_h1hi[2][NB * HD];
__device__ __align__(256) __nv_bfloat16 g_h1lo[2][NB * HD];
__device__ float g_c0[NB * HD];
__device__ float g_c1[NB * HD];
__device__ float g_cls_sum;
__device__ float g_bbox_sum;
__device__ int   g_correct;
__device__ unsigned g_bar_count;
__device__ unsigned g_bar_phase;            // monotonic across replays
__device__ unsigned g_grp_count[16 * 32];   // padded: one line per group
__device__ unsigned g_grp_phase[16 * 32];   // monotonic across replays

// ---------------- helpers ----------------------------------------------------
__device__ __forceinline__ uint32_t smem_u32(const void* p) {
    uint32_t a;
    asm("{ .reg .u64 t; cvta.to.shared.u64 t, %1; cvt.u32.u64 %0, t; }"
        : "=r"(a) : "l"(p));
    return a;
}
__device__ __forceinline__ void mma_bf16(float* d, const uint32_t* a,
                                         uint32_t b0, uint32_t b1) {
    asm volatile(
        "mma.sync.aligned.m16n8k16.row.col.f32.bf16.bf16.f32 "
        "{%0,%1,%2,%3}, {%4,%5,%6,%7}, {%8,%9}, {%0,%1,%2,%3};"
        : "+f"(d[0]), "+f"(d[1]), "+f"(d[2]), "+f"(d[3])
        : "r"(a[0]), "r"(a[1]), "r"(a[2]), "r"(a[3]), "r"(b0), "r"(b1));
}
__device__ __forceinline__ void ldsm_x4(uint32_t* r, uint32_t addr) {
    asm volatile("ldmatrix.sync.aligned.m8n8.x4.shared.b16 {%0,%1,%2,%3}, [%4];"
        : "=r"(r[0]), "=r"(r[1]), "=r"(r[2]), "=r"(r[3]) : "r"(addr));
}
#define CP16(dst, src) asm volatile("cp.async.cg.shared.global [%0], [%1], 16;" :: "r"(dst), "l"(src) : "memory")
#define CP_COMMIT()    asm volatile("cp.async.commit_group;" ::: "memory")
#define CP_WAIT0()     asm volatile("cp.async.wait_group 0;" ::: "memory")

// ---------------- barriers ----------------------------------------------------
__device__ __forceinline__ void grid_bar(unsigned& my_phase) {
    __syncthreads();
    if (threadIdx.x == 0) {
        __threadfence();
        unsigned old = atomicAdd(&g_bar_count, 1u);
        if (old == NBLK - 1) {
            g_bar_count = 0;
            __threadfence();
            atomicExch(&g_bar_phase, my_phase + 1u);
        } else {
            while (atomicAdd(&g_bar_phase, 0u) <= my_phase) __nanosleep(64);
        }
        __threadfence();
    }
    my_phase++;
    __syncthreads();
}
__device__ __forceinline__ void group_bar(int grp, unsigned& my_phase) {
    __syncthreads();
    if (threadIdx.x == 0) {
        __threadfence();
        unsigned old = atomicAdd(&g_grp_count[grp * 32], 1u);
        if (old == NGRP - 1) {
            g_grp_count[grp * 32] = 0;
            __threadfence();
            atomicExch(&g_grp_phase[grp * 32], my_phase + 1u);
        } else {
            while (atomicAdd(&g_grp_phase[grp * 32], 0u) <= my_phase) __nanosleep(32);
        }
        __threadfence();
    }
    my_phase++;
    __syncthreads();
}

// ---------------- one LSTM layer-step (all-cp.async feed) --------------------
// block tile: 64 batch rows x 32 j (128 gate cols). 8 warps = 2m x 4n.
// A: pre-split bf16 hi/lo in global -> cp.async. B: pre-split weights -> cp.async.
__device__ __forceinline__ void lstm_step(
    const __nv_bfloat16* __restrict__ xhi, const __nv_bfloat16* __restrict__ xlo,
    int xstr, int nch0,
    const __nv_bfloat16* __restrict__ hhi, const __nv_bfloat16* __restrict__ hlo,
    int wbase,
    const float* __restrict__ bias,
    float* __restrict__ cbuf,
    __nv_bfloat16* __restrict__ houthi, __nv_bfloat16* __restrict__ houtlo,
    uint32_t su)
{
    const int tid  = threadIdx.x;
    const int lane = tid & 31;
    const int w    = tid >> 5;
    const int m0w  = (w >> 2) * 32;
    const int n0w  = (w & 3) * 32;
    const int tr   = lane >> 2;
    const int tc   = lane & 3;
    const int row0 = (blockIdx.x >> 4) * 64;
    const int j0   = (blockIdx.x & 15) * 32;
    const int ntot = nch0 + HD / 64;
    const int lrow16 = lane & 15;
    const int lkoff  = (lane >> 4) << 2;

    // hoisted ldmatrix lane bases (byte offsets within a stage)
    const uint32_t aoff0 = (uint32_t)(((m0w + lrow16) * RSTRIDE + lkoff) * 4);
    const uint32_t aoff1 = (uint32_t)(((m0w + 16 + lrow16) * RSTRIDE + lkoff) * 4);
    const uint32_t boff0 = (uint32_t)(((n0w + lrow16) * RSTRIDE + lkoff) * 4);
    const uint32_t boff1 = (uint32_t)(((n0w + 16 + lrow16) * RSTRIDE + lkoff) * 4);

    float d[2][4][4];
    #pragma unroll
    for (int mf = 0; mf < 2; ++mf)
        #pragma unroll
        for (int nf = 0; nf < 4; ++nf)
            #pragma unroll
            for (int q = 0; q < 4; ++q) d[mf][nf][q] = 0.f;

    #define CP_A(kk_, s_)  do {                                                \
        const __nv_bfloat16* sH; const __nv_bfloat16* sL; int astr_, k0_;      \
        if ((kk_) < nch0) { sH = xhi; sL = xlo; astr_ = xstr; k0_ = (kk_) * 64; } \
        else              { sH = hhi; sL = hlo; astr_ = HD;   k0_ = ((kk_) - nch0) * 64; } \
        uint32_t aHiA = su + (uint32_t)((s_) * STAGE_U32) * 4u;                \
        uint32_t aLoA = aHiA + A_TILE_U32 * 4u;                                \
        _Pragma("unroll")                                                      \
        for (int l = 0; l < 2; ++l) {                                          \
            int idx = tid + l * 256; int r = idx >> 3, p = idx & 7;            \
            uint32_t doff = (uint32_t)(r * (RSTRIDE * 4) + p * 16);            \
            size_t soff = (size_t)(row0 + r) * astr_ + k0_ + p * 8;            \
            CP16(aHiA + doff, sH + soff);                                      \
            CP16(aLoA + doff, sL + soff);                                      \
        } } while (0)

    #define CP_B(kk_, s_)  do {                                                \
        const __nv_bfloat16* srcHi = g_whi + (size_t)(wbase + (kk_)) * WTILE;  \
        const __nv_bfloat16* srcLo = g_wlo + (size_t)(wbase + (kk_)) * WTILE;  \
        uint32_t bHiA = su + ((s_) * STAGE_U32 + 2 * A_TILE_U32) * 4u;         \
        uint32_t bLoA = bHiA + B_TILE_U32 * 4u;                                \
        _Pragma("unroll")                                                      \
        for (int l = 0; l < 4; ++l) {                                          \
            int idx = tid + l * 256; int r = idx >> 3, p = idx & 7;            \
            uint32_t doff = (uint32_t)(r * (RSTRIDE * 4) + p * 16);            \
            int soff = r * 64 + p * 8;                                         \
            CP16(bHiA + doff, srcHi + soff);                                   \
            CP16(bLoA + doff, srcLo + soff);                                   \
        } } while (0)

    // prologue: stage superchunk 0 into buffer 0
    CP_A(0, 0); CP_B(0, 0); CP_COMMIT();

    for (int kk = 0; kk < ntot; ++kk) {
        const int s = kk & 1;
        const bool pf = (kk + 1 < ntot);
        CP_WAIT0();                       // stage s landed
        __syncthreads();                  // publish stage s; retire readers of 1-s
        if (pf) { CP_A(kk + 1, 1 - s); CP_B(kk + 1, 1 - s); CP_COMMIT(); }

        const uint32_t stage = su + (uint32_t)(s * STAGE_U32) * 4u;
        const uint32_t bHiB  = stage + (2 * A_TILE_U32) * 4u;

        #pragma unroll
        for (int kg = 0; kg < 4; ++kg) {
            const uint32_t kbB = (uint32_t)(kg * 8 * 4);
            uint32_t ah[2][4], al[2][4];
            uint32_t bh[2][4], bl[2][4];
            {
                uint32_t a0 = stage + aoff0 + kbB;
                uint32_t a1 = stage + aoff1 + kbB;
                ldsm_x4(ah[0], a0);
                ldsm_x4(al[0], a0 + A_TILE_U32 * 4u);
                ldsm_x4(ah[1], a1);
                ldsm_x4(al[1], a1 + A_TILE_U32 * 4u);
                uint32_t b0 = bHiB + boff0 + kbB;
                uint32_t b1 = bHiB + boff1 + kbB;
                ldsm_x4(bh[0], b0);
                ldsm_x4(bl[0], b0 + B_TILE_U32 * 4u);
                ldsm_x4(bh[1], b1);
                ldsm_x4(bl[1], b1 + B_TILE_U32 * 4u);
            }
            #pragma unroll
            for (int nf = 0; nf < 4; ++nf) {
                const int np = nf >> 1, sel = nf & 1;
                uint32_t b0h = bh[np][sel], b1h = bh[np][sel + 2];
                uint32_t b0l = bl[np][sel], b1l = bl[np][sel + 2];
                #pragma unroll
                for (int mf = 0; mf < 2; ++mf) {
                    mma_bf16(d[mf][nf], ah[mf], b0h, b1h);
                    mma_bf16(d[mf][nf], ah[mf], b0l, b1l);
                    mma_bf16(d[mf][nf], al[mf], b0h, b1h);
                }
            }
        }
    }

    #undef CP_A
    #undef CP_B

    // epilogue: gate exchange + fused cell pointwise; h written as bf16 hi/lo
    #pragma unroll
    for (int mf = 0; mf < 2; ++mf) {
        #pragma unroll
        for (int nf = 0; nf < 4; ++nf) {
            float v0 = d[mf][nf][0], v1 = d[mf][nf][1];
            float v2 = d[mf][nf][2], v3 = d[mf][nf][3];
            float r0 = __shfl_xor_sync(0xffffffffu, v0, 1);
            float r1 = __shfl_xor_sync(0xffffffffu, v1, 1);
            float r2 = __shfl_xor_sync(0xffffffffu, v2, 1);
            float r3 = __shfl_xor_sync(0xffffffffu, v3, 1);
            if ((lane & 1) == 0) {
                int col = n0w + nf * 8 + tc * 2;
                int jj  = j0 + (col >> 2);
                int m   = row0 + m0w + mf * 16 + tr;
                float b0v = bias[jj], b1v = bias[HD + jj];
                float b2v = bias[2 * HD + jj], b3v = bias[3 * HD + jj];
                {
                    float gi = v0 + b0v, gf = v1 + b1v, gg = r0 + b2v, go = r1 + b3v;
                    float si = 1.f / (1.f + expf(-gi));
                    float sf = 1.f / (1.f + expf(-gf));
                    float so = 1.f / (1.f + expf(-go));
                    size_t ix = (size_t)m * HD + jj;
                    float cv = sf * cbuf[ix] + si * tanhf(gg);
                    cbuf[ix] = cv;
                    float hv = so * tanhf(cv);
                    __nv_bfloat16 hb = __float2bfloat16(hv);
                    houthi[ix] = hb;
                    houtlo[ix] = __float2bfloat16(hv - __bfloat162float(hb));
                }
                {
                    float gi = v2 + b0v, gf = v3 + b1v, gg = r2 + b2v, go = r3 + b3v;
                    float si = 1.f / (1.f + expf(-gi));
                    float sf = 1.f / (1.f + expf(-gf));
                    float so = 1.f / (1.f + expf(-go));
                    size_t ix = (size_t)(m + 8) * HD + jj;
                    float cv = sf * cbuf[ix] + si * tanhf(gg);
                    cbuf[ix] = cv;
                    float hv = so * tanhf(cv);
                    __nv_bfloat16 hb = __float2bfloat16(hv);
                    houthi[ix] = hb;
                    houtlo[ix] = __float2bfloat16(hv - __bfloat162float(hb));
                }
            }
        }
    }
}

// ---------------- whole network, one persistent kernel -----------------------
__global__ __launch_bounds__(NTHR, 2)
void rlstm_persistent(const float* __restrict__ data,
                      const int*   __restrict__ labels,
                      const float* __restrict__ props,
                      const float* __restrict__ Wih0, const float* __restrict__ Whh0,
                      const float* __restrict__ b0,
                      const float* __restrict__ Wih1, const float* __restrict__ Whh1,
                      const float* __restrict__ b1,
                      const float* __restrict__ Wcls, const float* __restrict__ bcls,
                      const float* __restrict__ Wbbox, const float* __restrict__ bbbox,
                      float* __restrict__ out)
{
    extern __shared__ uint32_t smU[];
    uint32_t su = smem_u32(smU);
    const int tid = threadIdx.x;
    const int grp = blockIdx.x >> 4;
    unsigned ph  = atomicAdd(&g_bar_phase, 0u);
    unsigned gph = atomicAdd(&g_grp_phase[grp * 32], 0u);

    // init states + loss accumulators
    const __nv_bfloat16 bz = __float2bfloat16(0.f);
    for (int i = blockIdx.x * NTHR + tid; i < NB * HD; i += NBLK * NTHR) {
        g_h0hi[0][i] = bz; g_h0lo[0][i] = bz;
        g_h1hi[0][i] = bz; g_h1lo[0][i] = bz;
        g_c0[i] = 0.f;     g_c1[i] = 0.f;
    }
    if (blockIdx.x == 0 && tid == 0) {
        g_cls_sum = 0.f; g_bbox_sum = 0.f; g_correct = 0;
    }
    // precompute hi/lo bf16 weights, packed [128][64] per (jt, superchunk)
    for (int i = blockIdx.x * NTHR + tid; i < WN; i += NBLK * NTHR) {
        int tile = i >> 13, e = i & 8191;
        int r = e >> 6, k = e & 63;
        int jt, kk;
        const float* B; int bstr, k0;
        if (tile < W0_TILES) {
            jt = tile / W0_NCH; kk = tile % W0_NCH;
            if (kk < 2) { B = Wih0; bstr = CH; k0 = kk * 64; }
            else        { B = Whh0; bstr = HD; k0 = (kk - 2) * 64; }
        } else {
            int t2 = tile - W0_TILES;
            jt = t2 / W1_NCH; kk = t2 % W1_NCH;
            if (kk < 8) { B = Wih1; bstr = HD; k0 = kk * 64; }
            else        { B = Whh1; bstr = HD; k0 = (kk - 8) * 64; }
        }
        int grow = (r & 3) * HD + jt * 32 + (r >> 2);
        float v = B[(size_t)grow * bstr + k0 + k];
        __nv_bfloat16 hb = __float2bfloat16(v);
        g_whi[i] = hb;
        g_wlo[i] = __float2bfloat16(v - __bfloat162float(hb));
    }
    // precompute x hi/lo split in [t][n][c] layout
    for (int i = blockIdx.x * NTHR + tid; i < SEQ * NB * CH; i += NBLK * NTHR) {
        int c = i & (CH - 1);
        int n = (i >> 7) & (NB - 1);
        int t = i >> 17;                      // CH*NB = 2^17
        float v = data[((size_t)n * SEQ + t) * CH + c];
        __nv_bfloat16 hb = __float2bfloat16(v);
        g_xhi[i] = hb;
        g_xlo[i] = __float2bfloat16(v - __bfloat162float(hb));
    }
    grid_bar(ph);

    const int jt = blockIdx.x & 15;
    const int wbase0 = jt * W0_NCH;
    const int wbase1 = W0_TILES + jt * W1_NCH;

    for (int t = 0; t < SEQ; ++t) {
        int p = t & 1;
        lstm_step(g_xhi + (size_t)t * NB * CH, g_xlo + (size_t)t * NB * CH,
                  CH, 2,
                  g_h0hi[p], g_h0lo[p],
                  wbase0, b0, g_c0, g_h0hi[1 - p], g_h0lo[1 - p], su);
        group_bar(grp, gph);
        lstm_step(g_h0hi[1 - p], g_h0lo[1 - p], HD, 8,
                  g_h1hi[p], g_h1lo[p],
                  wbase1, b1, g_c1, g_h1hi[1 - p], g_h1lo[1 - p], su);
        group_bar(grp, gph);
    }
    grid_bar(ph);   // all groups done before cross-group h1 reads

    // heads + loss on final hidden state (h1 buffer 0); 4 rows per block
    {
        float* hrow = (float*)smU;
        float* cls  = hrow + HD;
        for (int r = 0; r < 4; ++r) {
            int n = blockIdx.x * 4 + r;
            for (int j = tid; j < HD; j += NTHR)
                hrow[j] = __bfloat162float(g_h1hi[0][(size_t)n * HD + j]) +
                          __bfloat162float(g_h1lo[0][(size_t)n * HD + j]);
            __syncthreads();
            if (tid < NCLS) {
                float s = bcls[tid];
                const float* wp = Wcls + (size_t)tid * HD;
                #pragma unroll 8
                for (int j = 0; j < HD; ++j) s += hrow[j] * wp[j];
                cls[tid] = s;
            } else if (tid < NCLS + 2) {
                int pp = tid - NCLS;
                float s = bbbox[pp];
                const float* wp = Wbbox + (size_t)pp * HD;
                #pragma unroll 8
                for (int j = 0; j < HD; ++j) s += hrow[j] * wp[j];
                float tg = props[n * 2 + pp] * (1.0f / (float)SEQ);
                float dd = fabsf(s - tg);
                float sl = (dd < 1.f) ? 0.5f * dd * dd : dd - 0.5f;
                atomicAdd(&g_bbox_sum, sl);
            }
            __syncthreads();
            if (tid == 0) {
                float mx = cls[0]; int am = 0;
                for (int k = 1; k < NCLS; ++k)
                    if (cls[k] > mx) { mx = cls[k]; am = k; }
                float se = 0.f;
                for (int k = 0; k < NCLS; ++k) se += expf(cls[k] - mx);
                float lse = mx + logf(se);
                int lbl = labels[n * 2];
                atomicAdd(&g_cls_sum, -(cls[lbl] - lse));
                if (am == lbl) atomicAdd(&g_correct, 1);
            }
            __syncthreads();
        }
    }
    grid_bar(ph);

    if (blockIdx.x == 0 && tid == 0) {
        out[0] = (g_cls_sum / (float)NB) / (1.0f + (float)g_correct);
        out[1] = (g_bbox_sum / (float)(NB * 2)) * 10.0f;
    }
}

// ---------------- launch: ONE graph node -------------------------------------
extern "C" void kernel_launch(void* const* d_in, const int* in_sizes, int n_in,
                              void* d_out, int out_size) {
    const float* data   = (const float*)d_in[0];
    const int*   labels = (const int*)  d_in[1];
    const float* props  = (const float*)d_in[2];
    const float* Wih0   = (const float*)d_in[3];
    const float* Whh0   = (const float*)d_in[4];
    const float* b0     = (const float*)d_in[5];
    const float* Wih1   = (const float*)d_in[6];
    const float* Whh1   = (const float*)d_in[7];
    const float* b1     = (const float*)d_in[8];
    const float* Wcls   = (const float*)d_in[9];
    const float* bcls   = (const float*)d_in[10];
    const float* Wbbox  = (const float*)d_in[11];
    const float* bbbox  = (const float*)d_in[12];
    float* out = (float*)d_out;

    cudaFuncSetAttribute(rlstm_persistent,
                         cudaFuncAttributeMaxDynamicSharedMemorySize, SMEM_SZ);
    rlstm_persistent<<<NBLK, NTHR, SMEM_SZ>>>(data, labels, props,
                                              Wih0, Whh0, b0, Wih1, Whh1, b1,
                                              Wcls, bcls, Wbbox, bbbox, out);
}

// round 14
// speedup vs baseline: 1.0246x; 1.0246x over previous
#include <cuda_runtime.h>
#include <cuda_bf16.h>
#include <math.h>
#include <stdint.h>

#define HD    512
#define GATES 2048
#define NB    1024
#define SEQ   256
#define CH    128
#define NCLS  40
#define NBLK  256          // 16 m-tiles x 16 j-tiles, 2 CTAs/SM
#define NTHR  256
#define NGRP  16           // blocks per barrier group (same mt, all jt)

// smem stage (u32): 64-wide K superchunk. aHi|aLo (64 rows) + bHi|bLo (128 rows)
#define RSTRIDE 36                     // 32 data u32 + 4 pad
#define A_TILE_U32 (64 * RSTRIDE)      // 2304
#define B_TILE_U32 (128 * RSTRIDE)     // 4608
#define STAGE_U32 (2 * A_TILE_U32 + 2 * B_TILE_U32)   // 13824
#define SMEM_SZ (2 * STAGE_U32 * 4)    // 110592 bytes

// precomputed hi/lo bf16 weights, packed per (layer, jt, superchunk) tile [128][64]
#define W0_NCH 10
#define W1_NCH 16
#define W0_TILES (16 * W0_NCH)
#define W1_TILES (16 * W1_NCH)
#define WTILE 8192
#define WN ((W0_TILES + W1_TILES) * WTILE)

// ---------------- persistent device scratch ---------------------------------
__device__ __nv_bfloat16 g_whi[WN];
__device__ __nv_bfloat16 g_wlo[WN];
__device__ float g_h0[2][NB * HD];
__device__ float g_c0[NB * HD];
__device__ float g_h1[2][NB * HD];
__device__ float g_c1[NB * HD];
__device__ float g_cls_sum;
__device__ float g_bbox_sum;
__device__ int   g_correct;
__device__ unsigned g_bar_count;
__device__ unsigned g_bar_phase;            // monotonic across replays
__device__ unsigned g_grp_count[16 * 32];   // padded: one line per group
__device__ unsigned g_grp_phase[16 * 32];   // monotonic across replays

// ---------------- helpers ----------------------------------------------------
__device__ __forceinline__ uint32_t smem_u32(const void* p) {
    uint32_t a;
    asm("{ .reg .u64 t; cvta.to.shared.u64 t, %1; cvt.u32.u64 %0, t; }"
        : "=r"(a) : "l"(p));
    return a;
}
__device__ __forceinline__ uint32_t packbf(float x, float y) {
    uint32_t r;
    asm("cvt.rn.bf16x2.f32 %0, %1, %2;" : "=r"(r) : "f"(y), "f"(x));
    return r;   // low half = x, high half = y
}
__device__ __forceinline__ void mma_bf16(float* d, const uint32_t* a,
                                         uint32_t b0, uint32_t b1) {
    asm volatile(
        "mma.sync.aligned.m16n8k16.row.col.f32.bf16.bf16.f32 "
        "{%0,%1,%2,%3}, {%4,%5,%6,%7}, {%8,%9}, {%0,%1,%2,%3};"
        : "+f"(d[0]), "+f"(d[1]), "+f"(d[2]), "+f"(d[3])
        : "r"(a[0]), "r"(a[1]), "r"(a[2]), "r"(a[3]), "r"(b0), "r"(b1));
}
__device__ __forceinline__ void ldsm_x4(uint32_t* r, uint32_t addr) {
    asm volatile("ldmatrix.sync.aligned.m8n8.x4.shared.b16 {%0,%1,%2,%3}, [%4];"
        : "=r"(r[0]), "=r"(r[1]), "=r"(r[2]), "=r"(r[3]) : "r"(addr));
}
#define CP16(dst, src) asm volatile("cp.async.cg.shared.global [%0], [%1], 16;" :: "r"(dst), "l"(src) : "memory")
#define CP_COMMIT()    asm volatile("cp.async.commit_group;" ::: "memory")
#define CP_WAIT0()     asm volatile("cp.async.wait_group 0;" ::: "memory")

// ---------------- barriers ----------------------------------------------------
__device__ __forceinline__ void grid_bar(unsigned& my_phase) {
    __syncthreads();
    if (threadIdx.x == 0) {
        __threadfence();
        unsigned old = atomicAdd(&g_bar_count, 1u);
        if (old == NBLK - 1) {
            g_bar_count = 0;
            __threadfence();
            atomicExch(&g_bar_phase, my_phase + 1u);
        } else {
            while (atomicAdd(&g_bar_phase, 0u) <= my_phase) __nanosleep(64);
        }
        __threadfence();
    }
    my_phase++;
    __syncthreads();
}
__device__ __forceinline__ void group_bar(int grp, unsigned& my_phase) {
    __syncthreads();
    if (threadIdx.x == 0) {
        __threadfence();
        unsigned old = atomicAdd(&g_grp_count[grp * 32], 1u);
        if (old == NGRP - 1) {
            g_grp_count[grp * 32] = 0;
            __threadfence();
            atomicExch(&g_grp_phase[grp * 32], my_phase + 1u);
        } else {
            while (atomicAdd(&g_grp_phase[grp * 32], 0u) <= my_phase) __nanosleep(32);
        }
        __threadfence();
    }
    my_phase++;
    __syncthreads();
}

// ---------------- one LSTM layer-step (64-wide superchunks) ------------------
// block tile: 64 batch rows x 32 j (128 gate cols). 8 warps = 2m x 4n.
__device__ __forceinline__ void lstm_step(
    const float* __restrict__ X, int xstr, int Kx,
    const float* __restrict__ Hprev,
    int wbase,
    const float* __restrict__ bias,
    float* __restrict__ cbuf, float* __restrict__ hout,
    uint32_t* smU, uint32_t su)
{
    const int tid  = threadIdx.x;
    const int lane = tid & 31;
    const int w    = tid >> 5;
    const int m0w  = (w >> 2) * 32;
    const int n0w  = (w & 3) * 32;
    const int tr   = lane >> 2;
    const int tc   = lane & 3;
    const int row0 = (blockIdx.x >> 4) * 64;
    const int j0   = (blockIdx.x & 15) * 32;
    const int nch0 = Kx / 64;
    const int ntot = nch0 + HD / 64;
    const int lrow16 = lane & 15;
    const int lkoff  = (lane >> 4) << 2;

    // hoisted ldmatrix lane bases (u32 offsets within a stage)
    const uint32_t aoff0 = (uint32_t)(((m0w + lrow16) * RSTRIDE + lkoff) * 4);
    const uint32_t aoff1 = (uint32_t)(((m0w + 16 + lrow16) * RSTRIDE + lkoff) * 4);
    const uint32_t boff0 = (uint32_t)(((n0w + lrow16) * RSTRIDE + lkoff) * 4);
    const uint32_t boff1 = (uint32_t)(((n0w + 16 + lrow16) * RSTRIDE + lkoff) * 4);

    float d[2][4][4];
    #pragma unroll
    for (int mf = 0; mf < 2; ++mf)
        #pragma unroll
        for (int nf = 0; nf < 4; ++nf)
            #pragma unroll
            for (int q = 0; q < 4; ++q) d[mf][nf][q] = 0.f;

    float4 a4[4];

    #define LDG_A(kk_)  do {                                                   \
        const float* Ap; int astr_, k0_;                                       \
        if ((kk_) < nch0) { Ap = X;     astr_ = xstr; k0_ = (kk_) * 64; }      \
        else              { Ap = Hprev; astr_ = HD;   k0_ = ((kk_) - nch0) * 64; } \
        _Pragma("unroll")                                                      \
        for (int l = 0; l < 4; ++l) {                                          \
            int idx = tid + l * 256; int r = idx >> 4, fc = idx & 15;          \
            a4[l] = *reinterpret_cast<const float4*>(                          \
                &Ap[(size_t)(row0 + r) * astr_ + k0_ + fc * 4]);               \
        } } while (0)

    #define ST_A(s_)  do {                                                     \
        uint32_t* aHi = smU + (s_) * STAGE_U32;                                \
        uint32_t* aLo = aHi + A_TILE_U32;                                      \
        _Pragma("unroll")                                                      \
        for (int l = 0; l < 4; ++l) {                                          \
            int idx = tid + l * 256; int r = idx >> 4, fc = idx & 15;          \
            int so = r * RSTRIDE + fc * 2;                                     \
            float4 v = a4[l];                                                  \
            float hx = __bfloat162float(__float2bfloat16(v.x));                \
            float hy = __bfloat162float(__float2bfloat16(v.y));                \
            float hz = __bfloat162float(__float2bfloat16(v.z));                \
            float hw = __bfloat162float(__float2bfloat16(v.w));                \
            uint2 hv, lv;                                                      \
            hv.x = packbf(v.x, v.y);        hv.y = packbf(v.z, v.w);           \
            lv.x = packbf(v.x - hx, v.y - hy); lv.y = packbf(v.z - hz, v.w - hw); \
            *reinterpret_cast<uint2*>(&aHi[so]) = hv;                          \
            *reinterpret_cast<uint2*>(&aLo[so]) = lv;                          \
        } } while (0)

    #define CP_B(kk_, s_)  do {                                                \
        const __nv_bfloat16* srcHi = g_whi + (size_t)(wbase + (kk_)) * WTILE;  \
        const __nv_bfloat16* srcLo = g_wlo + (size_t)(wbase + (kk_)) * WTILE;  \
        uint32_t bHiA = su + ((s_) * STAGE_U32 + 2 * A_TILE_U32) * 4u;         \
        uint32_t bLoA = bHiA + B_TILE_U32 * 4u;                                \
        _Pragma("unroll")                                                      \
        for (int l = 0; l < 4; ++l) {                                          \
            int idx = tid + l * 256; int r = idx >> 3, p = idx & 7;            \
            uint32_t doff = (uint32_t)(r * (RSTRIDE * 4) + p * 16);            \
            int soff = r * 64 + p * 8;                                         \
            CP16(bHiA + doff, srcHi + soff);                                   \
            CP16(bLoA + doff, srcLo + soff);                                   \
        } } while (0)

    // prologue: stage superchunk 0 into buffer 0
    CP_B(0, 0); CP_COMMIT();
    LDG_A(0);
    ST_A(0);

    for (int kk = 0; kk < ntot; ++kk) {
        const int s = kk & 1;
        const bool pf = (kk + 1 < ntot);
        if (pf) LDG_A(kk + 1);            // long-latency global loads first
        CP_WAIT0();                       // B(kk) landed (only group in flight)
        __syncthreads();                  // publish stage s; retire readers of 1-s
        if (pf) { CP_B(kk + 1, 1 - s); CP_COMMIT(); }

        const uint32_t stage = su + (uint32_t)(s * STAGE_U32) * 4u;
        const uint32_t bHiB  = stage + (2 * A_TILE_U32) * 4u;

        #pragma unroll
        for (int kg = 0; kg < 4; ++kg) {
            const uint32_t kbB = (uint32_t)(kg * 8 * 4);   // bytes: kg*8 u32
            uint32_t ah[2][4], al[2][4];
            uint32_t bh[2][4], bl[2][4];
            {
                uint32_t a0 = stage + aoff0 + kbB;
                uint32_t a1 = stage + aoff1 + kbB;
                ldsm_x4(ah[0], a0);
                ldsm_x4(al[0], a0 + A_TILE_U32 * 4u);
                ldsm_x4(ah[1], a1);
                ldsm_x4(al[1], a1 + A_TILE_U32 * 4u);
                uint32_t b0 = bHiB + boff0 + kbB;
                uint32_t b1 = bHiB + boff1 + kbB;
                ldsm_x4(bh[0], b0);
                ldsm_x4(bl[0], b0 + B_TILE_U32 * 4u);
                ldsm_x4(bh[1], b1);
                ldsm_x4(bl[1], b1 + B_TILE_U32 * 4u);
            }
            // term-pass order: 8 independent MMAs between reuses of any
            // accumulator (HMMA RAW latency fully covered).
            #pragma unroll
            for (int nf = 0; nf < 4; ++nf) {
                const int np = nf >> 1, sel = nf & 1;
                #pragma unroll
                for (int mf = 0; mf < 2; ++mf)
                    mma_bf16(d[mf][nf], ah[mf], bh[np][sel], bh[np][sel + 2]);
            }
            #pragma unroll
            for (int nf = 0; nf < 4; ++nf) {
                const int np = nf >> 1, sel = nf & 1;
                #pragma unroll
                for (int mf = 0; mf < 2; ++mf)
                    mma_bf16(d[mf][nf], ah[mf], bl[np][sel], bl[np][sel + 2]);
            }
            #pragma unroll
            for (int nf = 0; nf < 4; ++nf) {
                const int np = nf >> 1, sel = nf & 1;
                #pragma unroll
                for (int mf = 0; mf < 2; ++mf)
                    mma_bf16(d[mf][nf], al[mf], bh[np][sel], bh[np][sel + 2]);
            }
        }

        if (pf) ST_A(1 - s);              // convert+store A(kk+1) into stage 1-s
    }

    #undef LDG_A
    #undef ST_A
    #undef CP_B

    // epilogue: gate exchange + fused cell pointwise
    #pragma unroll
    for (int mf = 0; mf < 2; ++mf) {
        #pragma unroll
        for (int nf = 0; nf < 4; ++nf) {
            float v0 = d[mf][nf][0], v1 = d[mf][nf][1];
            float v2 = d[mf][nf][2], v3 = d[mf][nf][3];
            float r0 = __shfl_xor_sync(0xffffffffu, v0, 1);
            float r1 = __shfl_xor_sync(0xffffffffu, v1, 1);
            float r2 = __shfl_xor_sync(0xffffffffu, v2, 1);
            float r3 = __shfl_xor_sync(0xffffffffu, v3, 1);
            if ((lane & 1) == 0) {
                int col = n0w + nf * 8 + tc * 2;
                int jj  = j0 + (col >> 2);
                int m   = row0 + m0w + mf * 16 + tr;
                float b0v = bias[jj], b1v = bias[HD + jj];
                float b2v = bias[2 * HD + jj], b3v = bias[3 * HD + jj];
                {
                    float gi = v0 + b0v, gf = v1 + b1v, gg = r0 + b2v, go = r1 + b3v;
                    float si = 1.f / (1.f + expf(-gi));
                    float sf = 1.f / (1.f + expf(-gf));
                    float so = 1.f / (1.f + expf(-go));
                    size_t ix = (size_t)m * HD + jj;
                    float cv = sf * cbuf[ix] + si * tanhf(gg);
                    cbuf[ix] = cv;
                    hout[ix] = so * tanhf(cv);
                }
                {
                    float gi = v2 + b0v, gf = v3 + b1v, gg = r2 + b2v, go = r3 + b3v;
                    float si = 1.f / (1.f + expf(-gi));
                    float sf = 1.f / (1.f + expf(-gf));
                    float so = 1.f / (1.f + expf(-go));
                    size_t ix = (size_t)(m + 8) * HD + jj;
                    float cv = sf * cbuf[ix] + si * tanhf(gg);
                    cbuf[ix] = cv;
                    hout[ix] = so * tanhf(cv);
                }
            }
        }
    }
}

// ---------------- whole network, one persistent kernel -----------------------
__global__ __launch_bounds__(NTHR, 2)
void rlstm_persistent(const float* __restrict__ data,
                      const int*   __restrict__ labels,
                      const float* __restrict__ props,
                      const float* __restrict__ Wih0, const float* __restrict__ Whh0,
                      const float* __restrict__ b0,
                      const float* __restrict__ Wih1, const float* __restrict__ Whh1,
                      const float* __restrict__ b1,
                      const float* __restrict__ Wcls, const float* __restrict__ bcls,
                      const float* __restrict__ Wbbox, const float* __restrict__ bbbox,
                      float* __restrict__ out)
{
    extern __shared__ uint32_t smU[];
    uint32_t su = smem_u32(smU);
    const int tid = threadIdx.x;
    const int grp = blockIdx.x >> 4;
    unsigned ph  = atomicAdd(&g_bar_phase, 0u);
    unsigned gph = atomicAdd(&g_grp_phase[grp * 32], 0u);

    for (int i = blockIdx.x * NTHR + tid; i < NB * HD; i += NBLK * NTHR) {
        g_h0[0][i] = 0.f; g_h1[0][i] = 0.f;
        g_c0[i] = 0.f;    g_c1[i] = 0.f;
    }
    if (blockIdx.x == 0 && tid == 0) {
        g_cls_sum = 0.f; g_bbox_sum = 0.f; g_correct = 0;
    }
    // precompute hi/lo bf16 weights, packed [128][64] per (jt, superchunk)
    for (int i = blockIdx.x * NTHR + tid; i < WN; i += NBLK * NTHR) {
        int tile = i >> 13, e = i & 8191;
        int r = e >> 6, k = e & 63;
        int jt, kk;
        const float* B; int bstr, k0;
        if (tile < W0_TILES) {
            jt = tile / W0_NCH; kk = tile % W0_NCH;
            if (kk < 2) { B = Wih0; bstr = CH; k0 = kk * 64; }
            else        { B = Whh0; bstr = HD; k0 = (kk - 2) * 64; }
        } else {
            int t2 = tile - W0_TILES;
            jt = t2 / W1_NCH; kk = t2 % W1_NCH;
            if (kk < 8) { B = Wih1; bstr = HD; k0 = kk * 64; }
            else        { B = Whh1; bstr = HD; k0 = (kk - 8) * 64; }
        }
        int grow = (r & 3) * HD + jt * 32 + (r >> 2);
        float v = B[(size_t)grow * bstr + k0 + k];
        __nv_bfloat16 hb = __float2bfloat16(v);
        g_whi[i] = hb;
        g_wlo[i] = __float2bfloat16(v - __bfloat162float(hb));
    }
    grid_bar(ph);

    const int jt = blockIdx.x & 15;
    const int wbase0 = jt * W0_NCH;
    const int wbase1 = W0_TILES + jt * W1_NCH;

    for (int t = 0; t < SEQ; ++t) {
        int p = t & 1;
        lstm_step(data + (size_t)t * CH, SEQ * CH, CH,
                  g_h0[p], wbase0, b0, g_c0, g_h0[1 - p], smU, su);
        group_bar(grp, gph);
        lstm_step(g_h0[1 - p], HD, HD,
                  g_h1[p], wbase1, b1, g_c1, g_h1[1 - p], smU, su);
        group_bar(grp, gph);
    }
    grid_bar(ph);   // all groups done before cross-group h1 reads

    // heads + loss on final hidden state g_h1[0]; 4 rows per block
    {
        float* hrow = (float*)smU;
        float* cls  = hrow + HD;
        for (int r = 0; r < 4; ++r) {
            int n = blockIdx.x * 4 + r;
            for (int j = tid; j < HD; j += NTHR)
                hrow[j] = g_h1[0][(size_t)n * HD + j];
            __syncthreads();
            if (tid < NCLS) {
                float s = bcls[tid];
                const float* wp = Wcls + (size_t)tid * HD;
                #pragma unroll 8
                for (int j = 0; j < HD; ++j) s += hrow[j] * wp[j];
                cls[tid] = s;
            } else if (tid < NCLS + 2) {
                int pp = tid - NCLS;
                float s = bbbox[pp];
                const float* wp = Wbbox + (size_t)pp * HD;
                #pragma unroll 8
                for (int j = 0; j < HD; ++j) s += hrow[j] * wp[j];
                float tg = props[n * 2 + pp] * (1.0f / (float)SEQ);
                float dd = fabsf(s - tg);
                float sl = (dd < 1.f) ? 0.5f * dd * dd : dd - 0.5f;
                atomicAdd(&g_bbox_sum, sl);
            }
            __syncthreads();
            if (tid == 0) {
                float mx = cls[0]; int am = 0;
                for (int k = 1; k < NCLS; ++k)
                    if (cls[k] > mx) { mx = cls[k]; am = k; }
                float se = 0.f;
                for (int k = 0; k < NCLS; ++k) se += expf(cls[k] - mx);
                float lse = mx + logf(se);
                int lbl = labels[n * 2];
                atomicAdd(&g_cls_sum, -(cls[lbl] - lse));
                if (am == lbl) atomicAdd(&g_correct, 1);
            }
            __syncthreads();
        }
    }
    grid_bar(ph);

    if (blockIdx.x == 0 && tid == 0) {
        out[0] = (g_cls_sum / (float)NB) / (1.0f + (float)g_correct);
        out[1] = (g_bbox_sum / (float)(NB * 2)) * 10.0f;
    }
}

// ---------------- launch: ONE graph node -------------------------------------
extern "C" void kernel_launch(void* const* d_in, const int* in_sizes, int n_in,
                              void* d_out, int out_size) {
    const float* data   = (const float*)d_in[0];
    const int*   labels = (const int*)  d_in[1];
    const float* props  = (const float*)d_in[2];
    const float* Wih0   = (const float*)d_in[3];
    const float* Whh0   = (const float*)d_in[4];
    const float* b0     = (const float*)d_in[5];
    const float* Wih1   = (const float*)d_in[6];
    const float* Whh1   = (const float*)d_in[7];
    const float* b1     = (const float*)d_in[8];
    const float* Wcls   = (const float*)d_in[9];
    const float* bcls   = (const float*)d_in[10];
    const float* Wbbox  = (const float*)d_in[11];
    const float* bbbox  = (const float*)d_in[12];
    float* out = (float*)d_out;

    cudaFuncSetAttribute(rlstm_persistent,
                         cudaFuncAttributeMaxDynamicSharedMemorySize, SMEM_SZ);
    rlstm_persistent<<<NBLK, NTHR, SMEM_SZ>>>(data, labels, props,
                                              Wih0, Whh0, b0, Wih1, Whh1, b1,
                                              Wcls, bcls, Wbbox, bbbox, out);
}

// round 15
// speedup vs baseline: 1.1271x; 1.1000x over previous
#include <cuda_runtime.h>
#include <cuda_bf16.h>
#include <math.h>
#include <stdint.h>

#define HD    512
#define GATES 2048
#define NB    1024
#define SEQ   256
#define CH    128
#define NCLS  40
#define NBLK  256          // 16 m-tiles x 16 j-tiles, 2 CTAs/SM
#define NTHR  256
#define NGRP  16           // blocks per barrier group (same mt, all jt)

// smem stage (u32): 64-wide K superchunk. aHi|aLo (64 rows) + bHi|bLo (128 rows)
#define RSTRIDE 36                     // 32 data u32 + 4 pad
#define A_TILE_U32 (64 * RSTRIDE)      // 2304
#define B_TILE_U32 (128 * RSTRIDE)     // 4608
#define STAGE_U32 (2 * A_TILE_U32 + 2 * B_TILE_U32)   // 13824
#define SMEM_SZ (2 * STAGE_U32 * 4)    // 110592 bytes

// precomputed hi/lo bf16 weights, packed per (layer, jt, superchunk) tile [128][64]
#define W0_NCH 10
#define W1_NCH 16
#define W0_TILES (16 * W0_NCH)
#define W1_TILES (16 * W1_NCH)
#define WTILE 8192
#define WN ((W0_TILES + W1_TILES) * WTILE)

// ---------------- persistent device scratch ---------------------------------
__device__ __nv_bfloat16 g_whi[WN];
__device__ __nv_bfloat16 g_wlo[WN];
__device__ float g_h0[2][NB * HD];
__device__ float g_c0[NB * HD];
__device__ float g_h1[2][NB * HD];
__device__ float g_c1[NB * HD];
__device__ float g_cls_sum;
__device__ float g_bbox_sum;
__device__ int   g_correct;
__device__ unsigned g_bar_count;
__device__ unsigned g_bar_phase;            // monotonic across replays
__device__ unsigned g_grp_count[16 * 32];   // padded: one line per group
__device__ unsigned g_grp_phase[16 * 32];   // monotonic across replays

// ---------------- helpers ----------------------------------------------------
__device__ __forceinline__ uint32_t smem_u32(const void* p) {
    uint32_t a;
    asm("{ .reg .u64 t; cvta.to.shared.u64 t, %1; cvt.u32.u64 %0, t; }"
        : "=r"(a) : "l"(p));
    return a;
}
__device__ __forceinline__ uint32_t packbf(float x, float y) {
    uint32_t r;
    asm("cvt.rn.bf16x2.f32 %0, %1, %2;" : "=r"(r) : "f"(y), "f"(x));
    return r;   // low half = x, high half = y
}
// fast sigmoid / tanh via ex2.approx + rcp.approx (rel err ~1e-6)
__device__ __forceinline__ float fsig(float x) {
    float e, r;
    asm("ex2.approx.ftz.f32 %0, %1;" : "=f"(e) : "f"(-1.4426950408889634f * x));
    asm("rcp.approx.ftz.f32 %0, %1;" : "=f"(r) : "f"(1.f + e));
    return r;
}
__device__ __forceinline__ float ftanh(float x) {
    float e, r;
    asm("ex2.approx.ftz.f32 %0, %1;" : "=f"(e) : "f"(-2.885390081777927f * x));
    asm("rcp.approx.ftz.f32 %0, %1;" : "=f"(r) : "f"(1.f + e));
    return 2.f * r - 1.f;
}
__device__ __forceinline__ void mma_bf16(float* d, const uint32_t* a,
                                         uint32_t b0, uint32_t b1) {
    asm volatile(
        "mma.sync.aligned.m16n8k16.row.col.f32.bf16.bf16.f32 "
        "{%0,%1,%2,%3}, {%4,%5,%6,%7}, {%8,%9}, {%0,%1,%2,%3};"
        : "+f"(d[0]), "+f"(d[1]), "+f"(d[2]), "+f"(d[3])
        : "r"(a[0]), "r"(a[1]), "r"(a[2]), "r"(a[3]), "r"(b0), "r"(b1));
}
__device__ __forceinline__ void ldsm_x4(uint32_t* r, uint32_t addr) {
    asm volatile("ldmatrix.sync.aligned.m8n8.x4.shared.b16 {%0,%1,%2,%3}, [%4];"
        : "=r"(r[0]), "=r"(r[1]), "=r"(r[2]), "=r"(r[3]) : "r"(addr));
}
#define CP16(dst, src) asm volatile("cp.async.cg.shared.global [%0], [%1], 16;" :: "r"(dst), "l"(src) : "memory")
#define CP_COMMIT()    asm volatile("cp.async.commit_group;" ::: "memory")
#define CP_WAIT0()     asm volatile("cp.async.wait_group 0;" ::: "memory")

// ---------------- barriers ----------------------------------------------------
__device__ __forceinline__ void grid_bar(unsigned& my_phase) {
    __syncthreads();
    if (threadIdx.x == 0) {
        __threadfence();
        unsigned old = atomicAdd(&g_bar_count, 1u);
        if (old == NBLK - 1) {
            g_bar_count = 0;
            __threadfence();
            atomicExch(&g_bar_phase, my_phase + 1u);
        } else {
            while (atomicAdd(&g_bar_phase, 0u) <= my_phase) __nanosleep(64);
        }
        __threadfence();
    }
    my_phase++;
    __syncthreads();
}
__device__ __forceinline__ void group_bar(int grp, unsigned& my_phase) {
    __syncthreads();
    if (threadIdx.x == 0) {
        __threadfence();
        unsigned old = atomicAdd(&g_grp_count[grp * 32], 1u);
        if (old == NGRP - 1) {
            g_grp_count[grp * 32] = 0;
            __threadfence();
            atomicExch(&g_grp_phase[grp * 32], my_phase + 1u);
        } else {
            int spins = 0;
            while (atomicAdd(&g_grp_phase[grp * 32], 0u) <= my_phase) {
                if (++spins > 4) __nanosleep(40);
            }
        }
        __threadfence();
    }
    my_phase++;
    __syncthreads();
}

// ---------------- one LSTM layer-step (64-wide superchunks) ------------------
// block tile: 64 batch rows x 32 j (128 gate cols). 8 warps = 2m x 4n.
__device__ __forceinline__ void lstm_step(
    const float* __restrict__ X, int xstr, int Kx,
    const float* __restrict__ Hprev,
    int wbase,
    const float* __restrict__ bias,
    float* __restrict__ cbuf, float* __restrict__ hout,
    uint32_t* smU, uint32_t su)
{
    const int tid  = threadIdx.x;
    const int lane = tid & 31;
    const int w    = tid >> 5;
    const int m0w  = (w >> 2) * 32;
    const int n0w  = (w & 3) * 32;
    const int tr   = lane >> 2;
    const int tc   = lane & 3;
    const int row0 = (blockIdx.x >> 4) * 64;
    const int j0   = (blockIdx.x & 15) * 32;
    const int nch0 = Kx / 64;
    const int ntot = nch0 + HD / 64;
    const int lrow16 = lane & 15;
    const int lkoff  = (lane >> 4) << 2;

    // hoisted ldmatrix lane bases (byte offsets within a stage)
    const uint32_t aoff0 = (uint32_t)(((m0w + lrow16) * RSTRIDE + lkoff) * 4);
    const uint32_t aoff1 = (uint32_t)(((m0w + 16 + lrow16) * RSTRIDE + lkoff) * 4);
    const uint32_t boff0 = (uint32_t)(((n0w + lrow16) * RSTRIDE + lkoff) * 4);
    const uint32_t boff1 = (uint32_t)(((n0w + 16 + lrow16) * RSTRIDE + lkoff) * 4);

    float d[2][4][4];
    #pragma unroll
    for (int mf = 0; mf < 2; ++mf)
        #pragma unroll
        for (int nf = 0; nf < 4; ++nf)
            #pragma unroll
            for (int q = 0; q < 4; ++q) d[mf][nf][q] = 0.f;

    float4 a4[4];

    #define LDG_A(kk_)  do {                                                   \
        const float* Ap; int astr_, k0_;                                       \
        if ((kk_) < nch0) { Ap = X;     astr_ = xstr; k0_ = (kk_) * 64; }      \
        else              { Ap = Hprev; astr_ = HD;   k0_ = ((kk_) - nch0) * 64; } \
        _Pragma("unroll")                                                      \
        for (int l = 0; l < 4; ++l) {                                          \
            int idx = tid + l * 256; int r = idx >> 4, fc = idx & 15;          \
            a4[l] = *reinterpret_cast<const float4*>(                          \
                &Ap[(size_t)(row0 + r) * astr_ + k0_ + fc * 4]);               \
        } } while (0)

    #define ST_A(s_)  do {                                                     \
        uint32_t* aHi = smU + (s_) * STAGE_U32;                                \
        uint32_t* aLo = aHi + A_TILE_U32;                                      \
        _Pragma("unroll")                                                      \
        for (int l = 0; l < 4; ++l) {                                          \
            int idx = tid + l * 256; int r = idx >> 4, fc = idx & 15;          \
            int so = r * RSTRIDE + fc * 2;                                     \
            float4 v = a4[l];                                                  \
            float hx = __bfloat162float(__float2bfloat16(v.x));                \
            float hy = __bfloat162float(__float2bfloat16(v.y));                \
            float hz = __bfloat162float(__float2bfloat16(v.z));                \
            float hw = __bfloat162float(__float2bfloat16(v.w));                \
            uint2 hv, lv;                                                      \
            hv.x = packbf(v.x, v.y);        hv.y = packbf(v.z, v.w);           \
            lv.x = packbf(v.x - hx, v.y - hy); lv.y = packbf(v.z - hz, v.w - hw); \
            *reinterpret_cast<uint2*>(&aHi[so]) = hv;                          \
            *reinterpret_cast<uint2*>(&aLo[so]) = lv;                          \
        } } while (0)

    #define CP_B(kk_, s_)  do {                                                \
        const __nv_bfloat16* srcHi = g_whi + (size_t)(wbase + (kk_)) * WTILE;  \
        const __nv_bfloat16* srcLo = g_wlo + (size_t)(wbase + (kk_)) * WTILE;  \
        uint32_t bHiA = su + ((s_) * STAGE_U32 + 2 * A_TILE_U32) * 4u;         \
        uint32_t bLoA = bHiA + B_TILE_U32 * 4u;                                \
        _Pragma("unroll")                                                      \
        for (int l = 0; l < 4; ++l) {                                          \
            int idx = tid + l * 256; int r = idx >> 3, p = idx & 7;            \
            uint32_t doff = (uint32_t)(r * (RSTRIDE * 4) + p * 16);            \
            int soff = r * 64 + p * 8;                                         \
            CP16(bHiA + doff, srcHi + soff);                                   \
            CP16(bLoA + doff, srcLo + soff);                                   \
        } } while (0)

    // guard smem-stage reuse against the previous (barrier-free) call
    __syncthreads();

    // prologue: stage superchunk 0 into buffer 0
    CP_B(0, 0); CP_COMMIT();
    LDG_A(0);
    ST_A(0);

    for (int kk = 0; kk < ntot; ++kk) {
        const int s = kk & 1;
        const bool pf = (kk + 1 < ntot);
        if (pf) LDG_A(kk + 1);            // long-latency global loads first
        CP_WAIT0();                       // B(kk) landed (only group in flight)
        __syncthreads();                  // publish stage s; retire readers of 1-s
        if (pf) { CP_B(kk + 1, 1 - s); CP_COMMIT(); }

        const uint32_t stage = su + (uint32_t)(s * STAGE_U32) * 4u;
        const uint32_t bHiB  = stage + (2 * A_TILE_U32) * 4u;

        #pragma unroll
        for (int kg = 0; kg < 4; ++kg) {
            const uint32_t kbB = (uint32_t)(kg * 8 * 4);   // bytes: kg*8 u32
            uint32_t ah[2][4], al[2][4];
            uint32_t bh[2][4], bl[2][4];
            {
                uint32_t a0 = stage + aoff0 + kbB;
                uint32_t a1 = stage + aoff1 + kbB;
                ldsm_x4(ah[0], a0);
                ldsm_x4(al[0], a0 + A_TILE_U32 * 4u);
                ldsm_x4(ah[1], a1);
                ldsm_x4(al[1], a1 + A_TILE_U32 * 4u);
                uint32_t b0 = bHiB + boff0 + kbB;
                uint32_t b1 = bHiB + boff1 + kbB;
                ldsm_x4(bh[0], b0);
                ldsm_x4(bl[0], b0 + B_TILE_U32 * 4u);
                ldsm_x4(bh[1], b1);
                ldsm_x4(bl[1], b1 + B_TILE_U32 * 4u);
            }
            #pragma unroll
            for (int nf = 0; nf < 4; ++nf) {
                const int np = nf >> 1, sel = nf & 1;
                #pragma unroll
                for (int mf = 0; mf < 2; ++mf)
                    mma_bf16(d[mf][nf], ah[mf], bh[np][sel], bh[np][sel + 2]);
            }
            #pragma unroll
            for (int nf = 0; nf < 4; ++nf) {
                const int np = nf >> 1, sel = nf & 1;
                #pragma unroll
                for (int mf = 0; mf < 2; ++mf)
                    mma_bf16(d[mf][nf], ah[mf], bl[np][sel], bl[np][sel + 2]);
            }
            #pragma unroll
            for (int nf = 0; nf < 4; ++nf) {
                const int np = nf >> 1, sel = nf & 1;
                #pragma unroll
                for (int mf = 0; mf < 2; ++mf)
                    mma_bf16(d[mf][nf], al[mf], bh[np][sel], bh[np][sel + 2]);
            }
        }

        if (pf) ST_A(1 - s);              // convert+store A(kk+1) into stage 1-s
    }

    #undef LDG_A
    #undef ST_A
    #undef CP_B

    // epilogue: gate exchange + fused cell pointwise (approx sigmoid/tanh)
    #pragma unroll
    for (int mf = 0; mf < 2; ++mf) {
        #pragma unroll
        for (int nf = 0; nf < 4; ++nf) {
            float v0 = d[mf][nf][0], v1 = d[mf][nf][1];
            float v2 = d[mf][nf][2], v3 = d[mf][nf][3];
            float r0 = __shfl_xor_sync(0xffffffffu, v0, 1);
            float r1 = __shfl_xor_sync(0xffffffffu, v1, 1);
            float r2 = __shfl_xor_sync(0xffffffffu, v2, 1);
            float r3 = __shfl_xor_sync(0xffffffffu, v3, 1);
            if ((lane & 1) == 0) {
                int col = n0w + nf * 8 + tc * 2;
                int jj  = j0 + (col >> 2);
                int m   = row0 + m0w + mf * 16 + tr;
                float b0v = bias[jj], b1v = bias[HD + jj];
                float b2v = bias[2 * HD + jj], b3v = bias[3 * HD + jj];
                {
                    float si = fsig(v0 + b0v);
                    float sf = fsig(v1 + b1v);
                    float so = fsig(r1 + b3v);
                    size_t ix = (size_t)m * HD + jj;
                    float cv = sf * cbuf[ix] + si * ftanh(r0 + b2v);
                    cbuf[ix] = cv;
                    hout[ix] = so * ftanh(cv);
                }
                {
                    float si = fsig(v2 + b0v);
                    float sf = fsig(v3 + b1v);
                    float so = fsig(r3 + b3v);
                    size_t ix = (size_t)(m + 8) * HD + jj;
                    float cv = sf * cbuf[ix] + si * ftanh(r2 + b2v);
                    cbuf[ix] = cv;
                    hout[ix] = so * ftanh(cv);
                }
            }
        }
    }
}

// ---------------- whole network, one persistent kernel -----------------------
__global__ __launch_bounds__(NTHR, 2)
void rlstm_persistent(const float* __restrict__ data,
                      const int*   __restrict__ labels,
                      const float* __restrict__ props,
                      const float* __restrict__ Wih0, const float* __restrict__ Whh0,
                      const float* __restrict__ b0,
                      const float* __restrict__ Wih1, const float* __restrict__ Whh1,
                      const float* __restrict__ b1,
                      const float* __restrict__ Wcls, const float* __restrict__ bcls,
                      const float* __restrict__ Wbbox, const float* __restrict__ bbbox,
                      float* __restrict__ out)
{
    extern __shared__ uint32_t smU[];
    uint32_t su = smem_u32(smU);
    const int tid = threadIdx.x;
    const int grp = blockIdx.x >> 4;
    unsigned ph  = atomicAdd(&g_bar_phase, 0u);
    unsigned gph = atomicAdd(&g_grp_phase[grp * 32], 0u);

    for (int i = blockIdx.x * NTHR + tid; i < NB * HD; i += NBLK * NTHR) {
        g_h0[0][i] = 0.f; g_h1[0][i] = 0.f;
        g_c0[i] = 0.f;    g_c1[i] = 0.f;
    }
    if (blockIdx.x == 0 && tid == 0) {
        g_cls_sum = 0.f; g_bbox_sum = 0.f; g_correct = 0;
    }
    // precompute hi/lo bf16 weights, packed [128][64] per (jt, superchunk)
    for (int i = blockIdx.x * NTHR + tid; i < WN; i += NBLK * NTHR) {
        int tile = i >> 13, e = i & 8191;
        int r = e >> 6, k = e & 63;
        int jt, kk;
        const float* B; int bstr, k0;
        if (tile < W0_TILES) {
            jt = tile / W0_NCH; kk = tile % W0_NCH;
            if (kk < 2) { B = Wih0; bstr = CH; k0 = kk * 64; }
            else        { B = Whh0; bstr = HD; k0 = (kk - 2) * 64; }
        } else {
            int t2 = tile - W0_TILES;
            jt = t2 / W1_NCH; kk = t2 % W1_NCH;
            if (kk < 8) { B = Wih1; bstr = HD; k0 = kk * 64; }
            else        { B = Whh1; bstr = HD; k0 = (kk - 8) * 64; }
        }
        int grow = (r & 3) * HD + jt * 32 + (r >> 2);
        float v = B[(size_t)grow * bstr + k0 + k];
        __nv_bfloat16 hb = __float2bfloat16(v);
        g_whi[i] = hb;
        g_wlo[i] = __float2bfloat16(v - __bfloat162float(hb));
    }
    grid_bar(ph);

    const int jt = blockIdx.x & 15;
    const int wbase0 = jt * W0_NCH;
    const int wbase1 = W0_TILES + jt * W1_NCH;

    // software-pipelined layers: one barrier per timestep.
    // span t: L1(t) then L0(t+1) — mutually independent; the bar at span end
    // guards all cross-block h reads of the next span (program order makes the
    // mid-step barrier redundant).
    lstm_step(data, SEQ * CH, CH, g_h0[0], wbase0, b0, g_c0, g_h0[1], smU, su);
    group_bar(grp, gph);
    for (int t = 0; t < SEQ; ++t) {
        int p = t & 1;
        lstm_step(g_h0[1 - p], HD, HD, g_h1[p], wbase1, b1, g_c1,
                  g_h1[1 - p], smU, su);
        if (t + 1 < SEQ)
            lstm_step(data + (size_t)(t + 1) * CH, SEQ * CH, CH,
                      g_h0[1 - p], wbase0, b0, g_c0, g_h0[p], smU, su);
        group_bar(grp, gph);
    }
    grid_bar(ph);   // all groups done before cross-group h1 reads

    // heads + loss on final hidden state g_h1[0]; 4 rows per block
    {
        float* hrow = (float*)smU;
        float* cls  = hrow + HD;
        for (int r = 0; r < 4; ++r) {
            int n = blockIdx.x * 4 + r;
            for (int j = tid; j < HD; j += NTHR)
                hrow[j] = g_h1[0][(size_t)n * HD + j];
            __syncthreads();
            if (tid < NCLS) {
                float s = bcls[tid];
                const float* wp = Wcls + (size_t)tid * HD;
                #pragma unroll 8
                for (int j = 0; j < HD; ++j) s += hrow[j] * wp[j];
                cls[tid] = s;
            } else if (tid < NCLS + 2) {
                int pp = tid - NCLS;
                float s = bbbox[pp];
                const float* wp = Wbbox + (size_t)pp * HD;
                #pragma unroll 8
                for (int j = 0; j < HD; ++j) s += hrow[j] * wp[j];
                float tg = props[n * 2 + pp] * (1.0f / (float)SEQ);
                float dd = fabsf(s - tg);
                float sl = (dd < 1.f) ? 0.5f * dd * dd : dd - 0.5f;
                atomicAdd(&g_bbox_sum, sl);
            }
            __syncthreads();
            if (tid == 0) {
                float mx = cls[0]; int am = 0;
                for (int k = 1; k < NCLS; ++k)
                    if (cls[k] > mx) { mx = cls[k]; am = k; }
                float se = 0.f;
                for (int k = 0; k < NCLS; ++k) se += expf(cls[k] - mx);
                float lse = mx + logf(se);
                int lbl = labels[n * 2];
                atomicAdd(&g_cls_sum, -(cls[lbl] - lse));
                if (am == lbl) atomicAdd(&g_correct, 1);
            }
            __syncthreads();
        }
    }
    grid_bar(ph);

    if (blockIdx.x == 0 && tid == 0) {
        out[0] = (g_cls_sum / (float)NB) / (1.0f + (float)g_correct);
        out[1] = (g_bbox_sum / (float)(NB * 2)) * 10.0f;
    }
}

// ---------------- launch: ONE graph node -------------------------------------
extern "C" void kernel_launch(void* const* d_in, const int* in_sizes, int n_in,
                              void* d_out, int out_size) {
    const float* data   = (const float*)d_in[0];
    const int*   labels = (const int*)  d_in[1];
    const float* props  = (const float*)d_in[2];
    const float* Wih0   = (const float*)d_in[3];
    const float* Whh0   = (const float*)d_in[4];
    const float* b0     = (const float*)d_in[5];
    const float* Wih1   = (const float*)d_in[6];
    const float* Whh1   = (const float*)d_in[7];
    const float* b1     = (const float*)d_in[8];
    const float* Wcls   = (const float*)d_in[9];
    const float* bcls   = (const float*)d_in[10];
    const float* Wbbox  = (const float*)d_in[11];
    const float* bbbox  = (const float*)d_in[12];
    float* out = (float*)d_out;

    cudaFuncSetAttribute(rlstm_persistent,
                         cudaFuncAttributeMaxDynamicSharedMemorySize, SMEM_SZ);
    rlstm_persistent<<<NBLK, NTHR, SMEM_SZ>>>(data, labels, props,
                                              Wih0, Whh0, b0, Wih1, Whh1, b1,
                                              Wcls, bcls, Wbbox, bbbox, out);
}

// round 16
// speedup vs baseline: 1.1273x; 1.0002x over previous
#include <cuda_runtime.h>
#include <cuda_bf16.h>
#include <math.h>
#include <stdint.h>

#define HD    512
#define GATES 2048
#define NB    1024
#define SEQ   256
#define CH    128
#define NCLS  40
#define NBLK  256          // 16 m-tiles x 16 j-tiles, 2 CTAs/SM
#define NTHR  256
#define NGRP  16           // blocks per barrier group (same mt, all jt)

// smem stage (u32): 64-wide K superchunk. aHi|aLo (64 rows) + bHi|bLo (128 rows)
#define RSTRIDE 36                     // 32 data u32 + 4 pad
#define A_TILE_U32 (64 * RSTRIDE)      // 2304
#define B_TILE_U32 (128 * RSTRIDE)     // 4608
#define STAGE_U32 (2 * A_TILE_U32 + 2 * B_TILE_U32)   // 13824
#define SMEM_SZ (2 * STAGE_U32 * 4)    // 110592 bytes

// precomputed hi/lo bf16 weights, packed per (layer, jt, superchunk) tile [128][64]
#define W0_NCH 10
#define W1_NCH 16
#define W0_TILES (16 * W0_NCH)
#define W1_TILES (16 * W1_NCH)
#define WTILE 8192
#define WN ((W0_TILES + W1_TILES) * WTILE)

// ---------------- persistent device scratch ---------------------------------
__device__ __nv_bfloat16 g_whi[WN];
__device__ __nv_bfloat16 g_wlo[WN];
__device__ float g_h0[2][NB * HD];
__device__ float g_c0[NB * HD];
__device__ float g_h1[2][NB * HD];
__device__ float g_c1[NB * HD];
__device__ float g_cls_sum;
__device__ float g_bbox_sum;
__device__ int   g_correct;
__device__ unsigned g_bar_count;
__device__ unsigned g_bar_phase;            // monotonic across replays
__device__ unsigned g_grp_count[16 * 32];   // padded: one line per group
__device__ unsigned g_grp_phase[16 * 32];   // monotonic across replays

// ---------------- helpers ----------------------------------------------------
__device__ __forceinline__ uint32_t smem_u32(const void* p) {
    uint32_t a;
    asm("{ .reg .u64 t; cvta.to.shared.u64 t, %1; cvt.u32.u64 %0, t; }"
        : "=r"(a) : "l"(p));
    return a;
}
__device__ __forceinline__ uint32_t packbf(float x, float y) {
    uint32_t r;
    asm("cvt.rn.bf16x2.f32 %0, %1, %2;" : "=r"(r) : "f"(y), "f"(x));
    return r;   // low half = x, high half = y
}
// fast sigmoid / tanh via ex2.approx + rcp.approx (rel err ~1e-6)
__device__ __forceinline__ float fsig(float x) {
    float e, r;
    asm("ex2.approx.ftz.f32 %0, %1;" : "=f"(e) : "f"(-1.4426950408889634f * x));
    asm("rcp.approx.ftz.f32 %0, %1;" : "=f"(r) : "f"(1.f + e));
    return r;
}
__device__ __forceinline__ float ftanh(float x) {
    float e, r;
    asm("ex2.approx.ftz.f32 %0, %1;" : "=f"(e) : "f"(-2.885390081777927f * x));
    asm("rcp.approx.ftz.f32 %0, %1;" : "=f"(r) : "f"(1.f + e));
    return 2.f * r - 1.f;
}
// NOTE: non-volatile — outputs are live; lets the compiler interleave freely.
__device__ __forceinline__ void mma_bf16(float* d, const uint32_t* a,
                                         uint32_t b0, uint32_t b1) {
    asm("mma.sync.aligned.m16n8k16.row.col.f32.bf16.bf16.f32 "
        "{%0,%1,%2,%3}, {%4,%5,%6,%7}, {%8,%9}, {%0,%1,%2,%3};"
        : "+f"(d[0]), "+f"(d[1]), "+f"(d[2]), "+f"(d[3])
        : "r"(a[0]), "r"(a[1]), "r"(a[2]), "r"(a[3]), "r"(b0), "r"(b1));
}
__device__ __forceinline__ void ldsm_x4(uint32_t* r, uint32_t addr) {
    asm volatile("ldmatrix.sync.aligned.m8n8.x4.shared.b16 {%0,%1,%2,%3}, [%4];"
        : "=r"(r[0]), "=r"(r[1]), "=r"(r[2]), "=r"(r[3]) : "r"(addr));
}
#define CP16(dst, src) asm volatile("cp.async.cg.shared.global [%0], [%1], 16;" :: "r"(dst), "l"(src) : "memory")
#define CP_COMMIT()    asm volatile("cp.async.commit_group;" ::: "memory")
#define CP_WAIT0()     asm volatile("cp.async.wait_group 0;" ::: "memory")

// ---------------- barriers ----------------------------------------------------
__device__ __forceinline__ void grid_bar(unsigned& my_phase) {
    __syncthreads();
    if (threadIdx.x == 0) {
        __threadfence();
        unsigned old = atomicAdd(&g_bar_count, 1u);
        if (old == NBLK - 1) {
            g_bar_count = 0;
            __threadfence();
            atomicExch(&g_bar_phase, my_phase + 1u);
        } else {
            while (atomicAdd(&g_bar_phase, 0u) <= my_phase) __nanosleep(64);
        }
        __threadfence();
    }
    my_phase++;
    __syncthreads();
}
__device__ __forceinline__ void group_bar(int grp, unsigned& my_phase) {
    __syncthreads();
    if (threadIdx.x == 0) {
        __threadfence();
        unsigned old = atomicAdd(&g_grp_count[grp * 32], 1u);
        if (old == NGRP - 1) {
            g_grp_count[grp * 32] = 0;
            __threadfence();
            atomicExch(&g_grp_phase[grp * 32], my_phase + 1u);
        } else {
            int spins = 0;
            while (atomicAdd(&g_grp_phase[grp * 32], 0u) <= my_phase) {
                if (++spins > 4) __nanosleep(40);
            }
        }
        __threadfence();
    }
    my_phase++;
    __syncthreads();
}

// ---------------- cell epilogue (bias + LSTM pointwise) ----------------------
__device__ __forceinline__ void cell_epilogue(
    float d[2][4][4], int lane, int m0w, int n0w, int tr, int tc,
    int row0, int j0, const float* __restrict__ bias,
    float* __restrict__ cbuf, float* __restrict__ hout)
{
    #pragma unroll
    for (int mf = 0; mf < 2; ++mf) {
        #pragma unroll
        for (int nf = 0; nf < 4; ++nf) {
            float v0 = d[mf][nf][0], v1 = d[mf][nf][1];
            float v2 = d[mf][nf][2], v3 = d[mf][nf][3];
            float r0 = __shfl_xor_sync(0xffffffffu, v0, 1);
            float r1 = __shfl_xor_sync(0xffffffffu, v1, 1);
            float r2 = __shfl_xor_sync(0xffffffffu, v2, 1);
            float r3 = __shfl_xor_sync(0xffffffffu, v3, 1);
            if ((lane & 1) == 0) {
                int col = n0w + nf * 8 + tc * 2;
                int jj  = j0 + (col >> 2);
                int m   = row0 + m0w + mf * 16 + tr;
                float b0v = bias[jj], b1v = bias[HD + jj];
                float b2v = bias[2 * HD + jj], b3v = bias[3 * HD + jj];
                {
                    float si = fsig(v0 + b0v);
                    float sf = fsig(v1 + b1v);
                    float so = fsig(r1 + b3v);
                    size_t ix = (size_t)m * HD + jj;
                    float cv = sf * cbuf[ix] + si * ftanh(r0 + b2v);
                    cbuf[ix] = cv;
                    hout[ix] = so * ftanh(cv);
                }
                {
                    float si = fsig(v2 + b0v);
                    float sf = fsig(v3 + b1v);
                    float so = fsig(r3 + b3v);
                    size_t ix = (size_t)(m + 8) * HD + jj;
                    float cv = sf * cbuf[ix] + si * ftanh(r2 + b2v);
                    cbuf[ix] = cv;
                    hout[ix] = so * ftanh(cv);
                }
            }
        }
    }
}

// ---------------- one fused span: L1(t) then L0(t+1), ONE pipeline -----------
// seg0 (n1 iters): gates for layer 1 at step t   (A: h0cur | h1prev, B: wb1)
// seg1 (n0 iters): gates for layer 0 at step t+1 (A: xnext | h0cur,  B: wb0)
// A chunk map (u): u<n1 ? (u<8 ? h0cur : h1prev)[..] : (v<2 ? xnext : h0cur)[..]
__device__ __forceinline__ void lstm_span(
    int n1, const float* __restrict__ h0cur, const float* __restrict__ h1prev,
    const float* __restrict__ bias1, float* __restrict__ c1,
    float* __restrict__ h1out, int wb1,
    int n0, const float* __restrict__ xnext,
    const float* __restrict__ bias0, float* __restrict__ c0,
    float* __restrict__ h0out, int wb0,
    uint32_t* smU, uint32_t su)
{
    const int tid  = threadIdx.x;
    const int lane = tid & 31;
    const int w    = tid >> 5;
    const int m0w  = (w >> 2) * 32;
    const int n0w  = (w & 3) * 32;
    const int tr   = lane >> 2;
    const int tc   = lane & 3;
    const int row0 = (blockIdx.x >> 4) * 64;
    const int j0   = (blockIdx.x & 15) * 32;
    const int nt   = n1 + n0;
    const int lrow16 = lane & 15;
    const int lkoff  = (lane >> 4) << 2;

    const uint32_t aoff0 = (uint32_t)(((m0w + lrow16) * RSTRIDE + lkoff) * 4);
    const uint32_t aoff1 = (uint32_t)(((m0w + 16 + lrow16) * RSTRIDE + lkoff) * 4);
    const uint32_t boff0 = (uint32_t)(((n0w + lrow16) * RSTRIDE + lkoff) * 4);
    const uint32_t boff1 = (uint32_t)(((n0w + 16 + lrow16) * RSTRIDE + lkoff) * 4);

    float d[2][4][4];
    #pragma unroll
    for (int mf = 0; mf < 2; ++mf)
        #pragma unroll
        for (int nf = 0; nf < 4; ++nf)
            #pragma unroll
            for (int q = 0; q < 4; ++q) d[mf][nf][q] = 0.f;

    float4 a4[4];

    #define LDG_A(u_)  do {                                                    \
        const float* Ap; int astr_, k0_;                                       \
        if ((u_) < n1) {                                                       \
            if ((u_) < 8) { Ap = h0cur;  astr_ = HD; k0_ = (u_) * 64; }        \
            else          { Ap = h1prev; astr_ = HD; k0_ = ((u_) - 8) * 64; }  \
        } else {                                                               \
            int v_ = (u_) - n1;                                                \
            if (v_ < 2) { Ap = xnext; astr_ = SEQ * CH; k0_ = v_ * 64; }       \
            else        { Ap = h0cur; astr_ = HD;       k0_ = (v_ - 2) * 64; } \
        }                                                                      \
        _Pragma("unroll")                                                      \
        for (int l = 0; l < 4; ++l) {                                          \
            int idx = tid + l * 256; int r = idx >> 4, fc = idx & 15;          \
            a4[l] = *reinterpret_cast<const float4*>(                          \
                &Ap[(size_t)(row0 + r) * astr_ + k0_ + fc * 4]);               \
        } } while (0)

    #define ST_A(s_)  do {                                                     \
        uint32_t* aHi = smU + (s_) * STAGE_U32;                                \
        uint32_t* aLo = aHi + A_TILE_U32;                                      \
        _Pragma("unroll")                                                      \
        for (int l = 0; l < 4; ++l) {                                          \
            int idx = tid + l * 256; int r = idx >> 4, fc = idx & 15;          \
            int so = r * RSTRIDE + fc * 2;                                     \
            float4 v = a4[l];                                                  \
            float hx = __bfloat162float(__float2bfloat16(v.x));                \
            float hy = __bfloat162float(__float2bfloat16(v.y));                \
            float hz = __bfloat162float(__float2bfloat16(v.z));                \
            float hw = __bfloat162float(__float2bfloat16(v.w));                \
            uint2 hv, lv;                                                      \
            hv.x = packbf(v.x, v.y);        hv.y = packbf(v.z, v.w);           \
            lv.x = packbf(v.x - hx, v.y - hy); lv.y = packbf(v.z - hz, v.w - hw); \
            *reinterpret_cast<uint2*>(&aHi[so]) = hv;                          \
            *reinterpret_cast<uint2*>(&aLo[so]) = lv;                          \
        } } while (0)

    #define CP_B(u_, s_)  do {                                                 \
        int wt_ = ((u_) < n1) ? (wb1 + (u_)) : (wb0 + (u_) - n1);              \
        const __nv_bfloat16* srcHi = g_whi + (size_t)wt_ * WTILE;              \
        const __nv_bfloat16* srcLo = g_wlo + (size_t)wt_ * WTILE;              \
        uint32_t bHiA = su + ((s_) * STAGE_U32 + 2 * A_TILE_U32) * 4u;         \
        uint32_t bLoA = bHiA + B_TILE_U32 * 4u;                                \
        _Pragma("unroll")                                                      \
        for (int l = 0; l < 4; ++l) {                                          \
            int idx = tid + l * 256; int r = idx >> 3, p = idx & 7;            \
            uint32_t doff = (uint32_t)(r * (RSTRIDE * 4) + p * 16);            \
            int soff = r * 64 + p * 8;                                         \
            CP16(bHiA + doff, srcHi + soff);                                   \
            CP16(bLoA + doff, srcLo + soff);                                   \
        } } while (0)

    // guard smem-stage reuse against the previous span's tail reads
    __syncthreads();

    // prologue: stage chunk 0 into buffer 0
    CP_B(0, 0); CP_COMMIT();
    LDG_A(0);
    ST_A(0);

    for (int u = 0; u < nt; ++u) {
        const int s = u & 1;
        const bool pf = (u + 1 < nt);
        if (pf) LDG_A(u + 1);
        CP_WAIT0();
        __syncthreads();
        if (pf) { CP_B(u + 1, 1 - s); CP_COMMIT(); }

        const uint32_t stage = su + (uint32_t)(s * STAGE_U32) * 4u;
        const uint32_t bHiB  = stage + (2 * A_TILE_U32) * 4u;

        #pragma unroll
        for (int kg = 0; kg < 4; ++kg) {
            const uint32_t kbB = (uint32_t)(kg * 8 * 4);
            uint32_t ah[2][4], al[2][4];
            uint32_t bh[2][4], bl[2][4];
            {
                uint32_t a0 = stage + aoff0 + kbB;
                uint32_t a1 = stage + aoff1 + kbB;
                ldsm_x4(ah[0], a0);
                ldsm_x4(al[0], a0 + A_TILE_U32 * 4u);
                ldsm_x4(ah[1], a1);
                ldsm_x4(al[1], a1 + A_TILE_U32 * 4u);
                uint32_t b0 = bHiB + boff0 + kbB;
                uint32_t b1 = bHiB + boff1 + kbB;
                ldsm_x4(bh[0], b0);
                ldsm_x4(bl[0], b0 + B_TILE_U32 * 4u);
                ldsm_x4(bh[1], b1);
                ldsm_x4(bl[1], b1 + B_TILE_U32 * 4u);
            }
            #pragma unroll
            for (int nf = 0; nf < 4; ++nf) {
                const int np = nf >> 1, sel = nf & 1;
                #pragma unroll
                for (int mf = 0; mf < 2; ++mf)
                    mma_bf16(d[mf][nf], ah[mf], bh[np][sel], bh[np][sel + 2]);
            }
            #pragma unroll
            for (int nf = 0; nf < 4; ++nf) {
                const int np = nf >> 1, sel = nf & 1;
                #pragma unroll
                for (int mf = 0; mf < 2; ++mf)
                    mma_bf16(d[mf][nf], ah[mf], bl[np][sel], bl[np][sel + 2]);
            }
            #pragma unroll
            for (int nf = 0; nf < 4; ++nf) {
                const int np = nf >> 1, sel = nf & 1;
                #pragma unroll
                for (int mf = 0; mf < 2; ++mf)
                    mma_bf16(d[mf][nf], al[mf], bh[np][sel], bh[np][sel + 2]);
            }
        }

        if (pf) ST_A(1 - s);

        // layer-1 epilogue mid-pipeline (seg1 fills already in flight)
        if (u == n1 - 1) {
            cell_epilogue(d, lane, m0w, n0w, tr, tc, row0, j0, bias1, c1, h1out);
            #pragma unroll
            for (int mf = 0; mf < 2; ++mf)
                #pragma unroll
                for (int nf = 0; nf < 4; ++nf)
                    #pragma unroll
                    for (int q = 0; q < 4; ++q) d[mf][nf][q] = 0.f;
        }
    }

    #undef LDG_A
    #undef ST_A
    #undef CP_B

    if (n0 > 0)
        cell_epilogue(d, lane, m0w, n0w, tr, tc, row0, j0, bias0, c0, h0out);
}

// ---------------- whole network, one persistent kernel -----------------------
__global__ __launch_bounds__(NTHR, 2)
void rlstm_persistent(const float* __restrict__ data,
                      const int*   __restrict__ labels,
                      const float* __restrict__ props,
                      const float* __restrict__ Wih0, const float* __restrict__ Whh0,
                      const float* __restrict__ b0,
                      const float* __restrict__ Wih1, const float* __restrict__ Whh1,
                      const float* __restrict__ b1,
                      const float* __restrict__ Wcls, const float* __restrict__ bcls,
                      const float* __restrict__ Wbbox, const float* __restrict__ bbbox,
                      float* __restrict__ out)
{
    extern __shared__ uint32_t smU[];
    uint32_t su = smem_u32(smU);
    const int tid = threadIdx.x;
    const int grp = blockIdx.x >> 4;
    unsigned ph  = atomicAdd(&g_bar_phase, 0u);
    unsigned gph = atomicAdd(&g_grp_phase[grp * 32], 0u);

    for (int i = blockIdx.x * NTHR + tid; i < NB * HD; i += NBLK * NTHR) {
        g_h0[0][i] = 0.f; g_h1[0][i] = 0.f;
        g_c0[i] = 0.f;    g_c1[i] = 0.f;
    }
    if (blockIdx.x == 0 && tid == 0) {
        g_cls_sum = 0.f; g_bbox_sum = 0.f; g_correct = 0;
    }
    // precompute hi/lo bf16 weights, packed [128][64] per (jt, superchunk)
    for (int i = blockIdx.x * NTHR + tid; i < WN; i += NBLK * NTHR) {
        int tile = i >> 13, e = i & 8191;
        int r = e >> 6, k = e & 63;
        int jt, kk;
        const float* B; int bstr, k0;
        if (tile < W0_TILES) {
            jt = tile / W0_NCH; kk = tile % W0_NCH;
            if (kk < 2) { B = Wih0; bstr = CH; k0 = kk * 64; }
            else        { B = Whh0; bstr = HD; k0 = (kk - 2) * 64; }
        } else {
            int t2 = tile - W0_TILES;
            jt = t2 / W1_NCH; kk = t2 % W1_NCH;
            if (kk < 8) { B = Wih1; bstr = HD; k0 = kk * 64; }
            else        { B = Whh1; bstr = HD; k0 = (kk - 8) * 64; }
        }
        int grow = (r & 3) * HD + jt * 32 + (r >> 2);
        float v = B[(size_t)grow * bstr + k0 + k];
        __nv_bfloat16 hb = __float2bfloat16(v);
        g_whi[i] = hb;
        g_wlo[i] = __float2bfloat16(v - __bfloat162float(hb));
    }
    grid_bar(ph);

    const int jt = blockIdx.x & 15;
    const int wbase0 = jt * W0_NCH;
    const int wbase1 = W0_TILES + jt * W1_NCH;

    // span -1: L0(0) only (n1 = 0)
    lstm_span(0, g_h0[0], nullptr, b1, g_c1, nullptr, wbase1,
              10, data, b0, g_c0, g_h0[1], wbase0, smU, su);
    group_bar(grp, gph);
    // span t: L1(t) + L0(t+1), one fused pipeline, one barrier
    for (int t = 0; t < SEQ; ++t) {
        int p = t & 1;
        const bool last = (t + 1 == SEQ);
        lstm_span(16, g_h0[1 - p], g_h1[p], b1, g_c1, g_h1[1 - p], wbase1,
                  last ? 0 : 10, data + (size_t)(t + 1) * CH,
                  b0, g_c0, g_h0[p], wbase0, smU, su);
        group_bar(grp, gph);
    }
    grid_bar(ph);   // all groups done before cross-group h1 reads

    // heads + loss on final hidden state g_h1[0]; 4 rows per block
    {
        float* hrow = (float*)smU;
        float* cls  = hrow + HD;
        for (int r = 0; r < 4; ++r) {
            int n = blockIdx.x * 4 + r;
            for (int j = tid; j < HD; j += NTHR)
                hrow[j] = g_h1[0][(size_t)n * HD + j];
            __syncthreads();
            if (tid < NCLS) {
                float s = bcls[tid];
                const float* wp = Wcls + (size_t)tid * HD;
                #pragma unroll 8
                for (int j = 0; j < HD; ++j) s += hrow[j] * wp[j];
                cls[tid] = s;
            } else if (tid < NCLS + 2) {
                int pp = tid - NCLS;
                float s = bbbox[pp];
                const float* wp = Wbbox + (size_t)pp * HD;
                #pragma unroll 8
                for (int j = 0; j < HD; ++j) s += hrow[j] * wp[j];
                float tg = props[n * 2 + pp] * (1.0f / (float)SEQ);
                float dd = fabsf(s - tg);
                float sl = (dd < 1.f) ? 0.5f * dd * dd : dd - 0.5f;
                atomicAdd(&g_bbox_sum, sl);
            }
            __syncthreads();
            if (tid == 0) {
                float mx = cls[0]; int am = 0;
                for (int k = 1; k < NCLS; ++k)
                    if (cls[k] > mx) { mx = cls[k]; am = k; }
                float se = 0.f;
                for (int k = 0; k < NCLS; ++k) se += expf(cls[k] - mx);
                float lse = mx + logf(se);
                int lbl = labels[n * 2];
                atomicAdd(&g_cls_sum, -(cls[lbl] - lse));
                if (am == lbl) atomicAdd(&g_correct, 1);
            }
            __syncthreads();
        }
    }
    grid_bar(ph);

    if (blockIdx.x == 0 && tid == 0) {
        out[0] = (g_cls_sum / (float)NB) / (1.0f + (float)g_correct);
        out[1] = (g_bbox_sum / (float)(NB * 2)) * 10.0f;
    }
}

// ---------------- launch: ONE graph node -------------------------------------
extern "C" void kernel_launch(void* const* d_in, const int* in_sizes, int n_in,
                              void* d_out, int out_size) {
    const float* data   = (const float*)d_in[0];
    const int*   labels = (const int*)  d_in[1];
    const float* props  = (const float*)d_in[2];
    const float* Wih0   = (const float*)d_in[3];
    const float* Whh0   = (const float*)d_in[4];
    const float* b0     = (const float*)d_in[5];
    const float* Wih1   = (const float*)d_in[6];
    const float* Whh1   = (const float*)d_in[7];
    const float* b1     = (const float*)d_in[8];
    const float* Wcls   = (const float*)d_in[9];
    const float* bcls   = (const float*)d_in[10];
    const float* Wbbox  = (const float*)d_in[11];
    const float* bbbox  = (const float*)d_in[12];
    float* out = (float*)d_out;

    cudaFuncSetAttribute(rlstm_persistent,
                         cudaFuncAttributeMaxDynamicSharedMemorySize, SMEM_SZ);
    rlstm_persistent<<<NBLK, NTHR, SMEM_SZ>>>(data, labels, props,
                                              Wih0, Whh0, b0, Wih1, Whh1, b1,
                                              Wcls, bcls, Wbbox, bbbox, out);
}